// round 1
// baseline (speedup 1.0000x reference)
#include <cuda_runtime.h>
#include <cstdint>
#include <cstddef>

// Conv 3x3 stride2 pad1: x[32,256,64,64] * w[256,256,3,3] -> out[32,256,32,32]
// Crop mask is all-ones (python slice clamping makes every zero segment empty).
// Implicit GEMM: M=32768 (b*1024+oh*32+ow), N=256 (cout), K=2304 (cin*9+kh*3+kw)
// TF32 mma.sync m16n8k8, tiles 128x128x16, double-buffered cp.async.

namespace {
constexpr int CIN  = 256;
constexpr int COUT = 256;
constexpr int Hin  = 64;
constexpr int Win  = 64;
constexpr int KTOT = CIN * 9;     // 2304
constexpr int BM = 128, BN = 128, BK = 16;
constexpr int PADK = 20;          // padded K-row length (floats) -> conflict-free frags
constexpr int NIT = KTOT / BK;    // 144
}

__global__ __launch_bounds__(256, 2)
void conv_tf32_kernel(const float* __restrict__ x,
                      const float* __restrict__ w,
                      float* __restrict__ out) {
  __shared__ float As[2][BM][PADK];
  __shared__ float Bs[2][BN][PADK];

  const int tid  = threadIdx.x;
  const int lane = tid & 31;
  const int warp = tid >> 5;
  const int wm = warp & 1;       // 2 warp-tiles in M (64 each)
  const int wn = warp >> 1;      // 4 warp-tiles in N (32 each)
  const int m0 = blockIdx.x * BM;
  const int n0 = blockIdx.y * BN;

  const int g  = lane >> 2;      // 0..7
  const int tg = lane & 3;       // 0..3

  float acc[4][4][4];
  #pragma unroll
  for (int mi = 0; mi < 4; ++mi)
    #pragma unroll
    for (int ni = 0; ni < 4; ++ni)
      #pragma unroll
      for (int r = 0; r < 4; ++r) acc[mi][ni][r] = 0.f;

  // A-gather mapping: thread owns one k-column (acol), 8 rows strided by 16
  const int acol  = tid & 15;
  const int arow0 = tid >> 4;    // 0..15
  // B mapping: thread loads 2x float4 of one weight row
  const int bn  = tid >> 1;      // 0..127
  const int bkq = (tid & 1) << 3; // 0 or 8

  auto load_stage = [&](int buf, int it) {
    const int k0 = it * BK;
    // ---- A: im2col gather via 4B cp.async (zero-fill for padding) ----
    int k   = k0 + acol;
    int cin = k / 9;
    int rem = k - cin * 9;
    int kh  = rem / 3;
    int kw  = rem - kh * 3;
    const float* xc = x + (size_t)cin * (Hin * Win);
    #pragma unroll
    for (int i = 0; i < 8; ++i) {
      int row = arow0 + (i << 4);
      int m   = m0 + row;
      int bimg = m >> 10;
      int oh   = (m >> 5) & 31;
      int ow   = m & 31;
      int ih = 2 * oh - 1 + kh;
      int iw = 2 * ow - 1 + kw;
      bool ok = ((unsigned)ih < (unsigned)Hin) && ((unsigned)iw < (unsigned)Win);
      const float* src = xc + (size_t)bimg * (CIN * Hin * Win) + ih * Win + iw;
      if (!ok) src = x;  // keep address valid; src-size=0 writes zeros
      unsigned dst = (unsigned)__cvta_generic_to_shared(&As[buf][row][acol]);
      int sz = ok ? 4 : 0;
      asm volatile("cp.async.ca.shared.global [%0], [%1], 4, %2;\n"
                   :: "r"(dst), "l"(src), "r"(sz));
    }
    // ---- B: weights [n][k] row-major, coalesced 16B ----
    const float* wsrc = w + (size_t)(n0 + bn) * KTOT + k0 + bkq;
    unsigned bdst = (unsigned)__cvta_generic_to_shared(&Bs[buf][bn][bkq]);
    asm volatile("cp.async.cg.shared.global [%0], [%1], 16;\n" :: "r"(bdst), "l"(wsrc));
    asm volatile("cp.async.cg.shared.global [%0], [%1], 16;\n" :: "r"(bdst + 16), "l"(wsrc + 4));
    asm volatile("cp.async.commit_group;\n");
  };

  load_stage(0, 0);

  for (int it = 0; it < NIT; ++it) {
    asm volatile("cp.async.wait_group 0;\n");
    __syncthreads();   // stage(it) visible; all threads done computing it-1
    if (it + 1 < NIT) load_stage((it + 1) & 1, it + 1);

    const float (*A)[PADK]  = As[it & 1];
    const float (*Bm)[PADK] = Bs[it & 1];

    #pragma unroll
    for (int ks = 0; ks < BK / 8; ++ks) {
      const int kk = ks * 8;
      unsigned a[4][4], b[4][2];
      #pragma unroll
      for (int mi = 0; mi < 4; ++mi) {
        int r = wm * 64 + mi * 16 + g;
        float f0 = A[r][kk + tg];
        float f1 = A[r + 8][kk + tg];
        float f2 = A[r][kk + tg + 4];
        float f3 = A[r + 8][kk + tg + 4];
        asm volatile("cvt.rna.tf32.f32 %0, %1;" : "=r"(a[mi][0]) : "f"(f0));
        asm volatile("cvt.rna.tf32.f32 %0, %1;" : "=r"(a[mi][1]) : "f"(f1));
        asm volatile("cvt.rna.tf32.f32 %0, %1;" : "=r"(a[mi][2]) : "f"(f2));
        asm volatile("cvt.rna.tf32.f32 %0, %1;" : "=r"(a[mi][3]) : "f"(f3));
      }
      #pragma unroll
      for (int ni = 0; ni < 4; ++ni) {
        int r = wn * 32 + ni * 8 + g;
        float f0 = Bm[r][kk + tg];
        float f1 = Bm[r][kk + tg + 4];
        asm volatile("cvt.rna.tf32.f32 %0, %1;" : "=r"(b[ni][0]) : "f"(f0));
        asm volatile("cvt.rna.tf32.f32 %0, %1;" : "=r"(b[ni][1]) : "f"(f1));
      }
      #pragma unroll
      for (int mi = 0; mi < 4; ++mi)
        #pragma unroll
        for (int ni = 0; ni < 4; ++ni) {
          asm volatile(
            "mma.sync.aligned.m16n8k8.row.col.f32.tf32.tf32.f32 "
            "{%0,%1,%2,%3}, {%4,%5,%6,%7}, {%8,%9}, {%0,%1,%2,%3};"
            : "+f"(acc[mi][ni][0]), "+f"(acc[mi][ni][1]),
              "+f"(acc[mi][ni][2]), "+f"(acc[mi][ni][3])
            : "r"(a[mi][0]), "r"(a[mi][1]), "r"(a[mi][2]), "r"(a[mi][3]),
              "r"(b[ni][0]), "r"(b[ni][1]));
        }
    }
  }

  // Epilogue: out[b][n][oh][ow]; idx = b*COUT*1024 + n*1024 + (m & 1023)
  #pragma unroll
  for (int mi = 0; mi < 4; ++mi) {
    int mrow = m0 + wm * 64 + mi * 16 + g;   // mrow and mrow+8 share the same image
    int bimg = mrow >> 10;
    int sp   = mrow & 1023;
    #pragma unroll
    for (int ni = 0; ni < 4; ++ni) {
      int n = n0 + wn * 32 + ni * 8 + 2 * tg;
      float* o0 = out + ((size_t)bimg * COUT + n) * 1024;
      o0[sp]            = acc[mi][ni][0];
      o0[1024 + sp]     = acc[mi][ni][1];
      o0[sp + 8]        = acc[mi][ni][2];
      o0[1024 + sp + 8] = acc[mi][ni][3];
    }
  }
}

extern "C" void kernel_launch(void* const* d_in, const int* in_sizes, int n_in,
                              void* d_out, int out_size) {
  (void)out_size;
  const float* x = (const float*)d_in[0];
  const float* w = (const float*)d_in[1];
  // Defensive: identify tensors by size (x has 33.5M elems, w 589824)
  if (n_in >= 2 && in_sizes[0] < in_sizes[1]) {
    x = (const float*)d_in[1];
    w = (const float*)d_in[0];
  }
  dim3 grid(32768 / BM, COUT / BN);  // (256, 2)
  conv_tf32_kernel<<<grid, 256>>>(x, w, (float*)d_out);
}

// round 3
// speedup vs baseline: 1.2262x; 1.2262x over previous
#include <cuda_runtime.h>
#include <cstdint>
#include <cstddef>

// Conv 3x3 s2 p1: x[32,256,64,64] * w[256,256,3,3] -> out[32,256,32,32]
// (crop mask is all-ones: python slice clamping empties every zero segment).
// Implicit GEMM M=32768, N=256, K=2304 re-enumerated k'=(kh*3+kw)*256+cin.
// Legacy tensor path (tcgen05 unavailable at this PTX target):
// mma.sync.m16n8k8.tf32, CTA tile 128x256x16, fragment-layout smem,
// pure-cp.async producer, 3-stage pipeline. All tf32 rounding in prepasses.

namespace {
constexpr int NIT = 144;                 // 2304 / 16
constexpr int A_STAGE = 8192;            // 128 x 16 x 4B
constexpr int B_STAGE = 16384;           // 256 x 16 x 4B
constexpr int SM_A = 0;
constexpr int SM_B = 3 * A_STAGE;        // 24576
constexpr int SMEM_BYTES = SM_B + 3 * B_STAGE;  // 73728
}

// Scratch (sanctioned __device__ globals):
// xT[b][cin][ih][par][32] : x tf32-rounded, iw split into even/odd planes
__device__ float xT[33554432];
// wT fragment layout: [stage s][ns][lane][pos]
//   s = k'>>4, ns = n>>3, lane = (n&7)*4 + (c&3), pos = c>>2  (c = k'&15)
__device__ float wT[589824];

__device__ __forceinline__ uint32_t smem_u32(const void* p) {
  uint32_t a;
  asm("{ .reg .u64 t; cvta.to.shared.u64 t, %1; cvt.u32.u64 %0, t; }" : "=r"(a) : "l"(p));
  return a;
}

__global__ void prep_x(const float* __restrict__ x) {
  int i = blockIdx.x * 256 + threadIdx.x;        // grid exactly covers 33554432
  float v = x[i];
  uint32_t t;
  asm("cvt.rna.tf32.f32 %0, %1;" : "=r"(t) : "f"(v));
  int iw = i & 63;
  int base = i >> 6;                              // (b*256+cin)*64 + ih
  xT[(base << 6) + ((iw & 1) << 5) + (iw >> 1)] = __uint_as_float(t);
}

__global__ void prep_w(const float* __restrict__ w) {
  int i = blockIdx.x * 256 + threadIdx.x;        // grid exactly covers 589824
  float v = w[i];
  uint32_t t;
  asm("cvt.rna.tf32.f32 %0, %1;" : "=r"(t) : "f"(v));
  int n = i / 2304;
  int r = i - n * 2304;
  int cin = r / 9;
  int t9 = r - cin * 9;
  int kp = t9 * 256 + cin;                        // k'
  int s = kp >> 4, c = kp & 15;
  wT[s * 4096 + (n >> 3) * 128 + (n & 7) * 16 + (c & 3) * 4 + (c >> 2)] =
      __uint_as_float(t);
}

__device__ __forceinline__ void lds128(uint32_t* r, uint32_t a) {
  asm volatile("ld.shared.v4.b32 {%0,%1,%2,%3}, [%4];"
               : "=r"(r[0]), "=r"(r[1]), "=r"(r[2]), "=r"(r[3]) : "r"(a));
}
__device__ __forceinline__ void mma8(float* c, const uint32_t* a, uint32_t b0, uint32_t b1) {
  asm volatile(
      "mma.sync.aligned.m16n8k8.row.col.f32.tf32.tf32.f32 "
      "{%0,%1,%2,%3}, {%4,%5,%6,%7}, {%8,%9}, {%0,%1,%2,%3};"
      : "+f"(c[0]), "+f"(c[1]), "+f"(c[2]), "+f"(c[3])
      : "r"(a[0]), "r"(a[1]), "r"(a[2]), "r"(a[3]), "r"(b0), "r"(b1));
}

__global__ __launch_bounds__(256, 1)
void conv_main(float* __restrict__ out) {
  extern __shared__ char dsm[];
  const uint32_t sb = smem_u32(dsm);
  const int tid = threadIdx.x, lane = tid & 31, warp = tid >> 5;
  const int wm = warp & 1, wn = warp >> 1;       // 2 (M) x 4 (N) warps
  const int m0 = blockIdx.x * 128;
  const int bimg = m0 >> 10;

  // ---- producer-side constants (thread = row r, k-half ks) ----
  const int pr = tid >> 1;                        // 0..127
  const int pks = tid & 1;
  const int pm = m0 + pr;
  const int poh = (pm >> 5) & 31, pow_ = pm & 31;
  const int prr = pr & 15;
  // A fragment slot base: block (ms*2+ks)*512B + lane(g*4+tg)*16 + slot(hi+2*half)*4
  const uint32_t a_off = (uint32_t)(((pr >> 4) * 2 + pks) * 512 + (prr & 7) * 64
                                    + (prr >> 3) * 4);
  const float* xb = xT + ((size_t)bimg * 256) * 4096;

  float acc[4][8][4];
#pragma unroll
  for (int mi = 0; mi < 4; ++mi)
#pragma unroll
    for (int ni = 0; ni < 8; ++ni)
#pragma unroll
      for (int q = 0; q < 4; ++q) acc[mi][ni][q] = 0.f;

  auto load_stage = [&](int s, int buf) {
    // ---- A: 8x 4B cp.async into fragment slots, single predicate ----
    const int tap = s >> 4;
    const int cinb = (s & 15) << 4;
    const int kh = tap / 3, kw = tap - kh * 3;
    const int ih = 2 * poh - 1 + kh;
    const int iw = 2 * pow_ - 1 + kw;
    const bool ok = ((unsigned)ih < 64u) && ((unsigned)iw < 64u);
    const float* src = ok ? (xb + (size_t)(cinb + pks * 8) * 4096 + ih * 64
                             + (iw & 1) * 32 + (iw >> 1))
                          : (const float*)xT;
    const int sz = ok ? 4 : 0;
    const uint32_t ab = sb + SM_A + buf * A_STAGE + a_off;
    // j = half*4 + tg; dst offset = tg*16 + half*8 ; src offset = j*4096 floats
#pragma unroll
    for (int half = 0; half < 2; ++half)
#pragma unroll
      for (int tg = 0; tg < 4; ++tg) {
        const uint32_t dst = ab + tg * 16 + half * 8;
        const float* sp = src + (size_t)(half * 4 + tg) * 4096;
        asm volatile("cp.async.ca.shared.global [%0], [%1], 4, %2;\n"
                     :: "r"(dst), "l"(sp), "r"(sz));
      }
    // ---- B: identity copy of the 16KB stage block ----
    const float* bsrc = wT + (size_t)s * 4096 + tid * 4;
    const uint32_t bdst = sb + SM_B + buf * B_STAGE + tid * 16;
#pragma unroll
    for (int it = 0; it < 4; ++it)
      asm volatile("cp.async.cg.shared.global [%0], [%1], 16;\n"
                   :: "r"(bdst + it * 4096), "l"(bsrc + it * 1024));
  };

  load_stage(0, 0);
  asm volatile("cp.async.commit_group;\n");
  load_stage(1, 1);
  asm volatile("cp.async.commit_group;\n");

  int buf = 0, buf2 = 2;   // buf = s%3, buf2 = (s+2)%3
  for (int s = 0; s < NIT; ++s) {
    asm volatile("cp.async.wait_group 1;\n" ::: "memory");
    __syncthreads();
    if (s + 2 < NIT) load_stage(s + 2, buf2);
    asm volatile("cp.async.commit_group;\n");

    const uint32_t ab = sb + SM_A + buf * A_STAGE + wm * 4096 + lane * 16;
    const uint32_t bb = sb + SM_B + buf * B_STAGE + wn * 4096 + lane * 16;
    uint32_t a[4][2][4];
#pragma unroll
    for (int mi = 0; mi < 4; ++mi)
#pragma unroll
      for (int ks = 0; ks < 2; ++ks)
        lds128(a[mi][ks], ab + (mi * 2 + ks) * 512);
#pragma unroll
    for (int ni = 0; ni < 8; ++ni) {
      uint32_t b[4];
      lds128(b, bb + ni * 512);
#pragma unroll
      for (int mi = 0; mi < 4; ++mi) {
        mma8(acc[mi][ni], a[mi][0], b[0], b[1]);
        mma8(acc[mi][ni], a[mi][1], b[2], b[3]);
      }
    }
    buf = (buf == 2) ? 0 : buf + 1;
    buf2 = (buf2 == 2) ? 0 : buf2 + 1;
  }

  // ---- epilogue: out[b][n][oh][ow] ----
  const int g = lane >> 2, tg = lane & 3;
#pragma unroll
  for (int mi = 0; mi < 4; ++mi) {
    const int mrow = m0 + wm * 64 + mi * 16 + g;
    const int sp = mrow & 1023;
#pragma unroll
    for (int ni = 0; ni < 8; ++ni) {
      const int n = wn * 64 + ni * 8 + 2 * tg;
      float* o0 = out + ((size_t)bimg * 256 + n) * 1024;
      o0[sp]            = acc[mi][ni][0];
      o0[1024 + sp]     = acc[mi][ni][1];
      o0[sp + 8]        = acc[mi][ni][2];
      o0[1024 + sp + 8] = acc[mi][ni][3];
    }
  }
}

extern "C" void kernel_launch(void* const* d_in, const int* in_sizes, int n_in,
                              void* d_out, int out_size) {
  (void)out_size;
  const float* x = (const float*)d_in[0];
  const float* w = (const float*)d_in[1];
  if (n_in >= 2 && in_sizes[0] < in_sizes[1]) {  // defensive ordering by size
    x = (const float*)d_in[1];
    w = (const float*)d_in[0];
  }
  cudaFuncSetAttribute(conv_main, cudaFuncAttributeMaxDynamicSharedMemorySize,
                       SMEM_BYTES);
  prep_x<<<131072, 256>>>(x);
  prep_w<<<2304, 256>>>(w);
  conv_main<<<256, 256, SMEM_BYTES>>>((float*)d_out);
}

// round 4
// speedup vs baseline: 1.2448x; 1.0152x over previous
#include <cuda_runtime.h>
#include <cstdint>
#include <cstddef>

// Conv 3x3 s2 p1: x[32,256,64,64] * w[256,256,3,3] -> out[32,256,32,32]
// (crop mask is all-ones: python slice clamping empties every zero segment).
// Implicit GEMM M=32768, N=256, K=2304 re-enumerated k'=(kh*3+kw)*256+cin.
// Legacy tensor path (tcgen05 not accepted at this PTX target):
// mma.sync.m16n8k8.tf32, CTA tile 128x128x16, fragment-layout smem,
// pure-cp.async producer, 3-stage pipeline, 2 CTAs/SM for latency hiding.

namespace {
constexpr int NIT = 144;                 // 2304 / 16
constexpr int A_STAGE = 8192;            // 128 x 16 x 4B
constexpr int B_STAGE = 8192;            // 128 x 16 x 4B
constexpr int SM_A = 0;
constexpr int SM_B = 3 * A_STAGE;        // 24576
constexpr int SMEM_BYTES = SM_B + 3 * B_STAGE;  // 49152
}

// Scratch (sanctioned __device__ globals):
// xT[b][cin][ih][par][32] : x tf32-rounded, iw split into even/odd planes
__device__ float xT[33554432];
// wT fragment layout: [stage s][ns][lane][pos]
//   s = k'>>4, ns = n>>3, lane = (n&7)*4 + (c&3), pos = c>>2  (c = k'&15)
__device__ float wT[589824];

__device__ __forceinline__ uint32_t smem_u32(const void* p) {
  uint32_t a;
  asm("{ .reg .u64 t; cvta.to.shared.u64 t, %1; cvt.u32.u64 %0, t; }" : "=r"(a) : "l"(p));
  return a;
}

// Vectorized: float4 in, two float2 out (even/odd planes stay contiguous
// because an aligned iw-quad {e,e+1,e+2,e+3} maps to pairs {e/2,e/2+1}).
__global__ void prep_x(const float4* __restrict__ x4) {
  int i = blockIdx.x * 256 + threadIdx.x;   // grid covers 8388608 float4s
  float4 v = x4[i];
  uint32_t t0, t1, t2, t3;
  asm("cvt.rna.tf32.f32 %0, %1;" : "=r"(t0) : "f"(v.x));
  asm("cvt.rna.tf32.f32 %0, %1;" : "=r"(t1) : "f"(v.y));
  asm("cvt.rna.tf32.f32 %0, %1;" : "=r"(t2) : "f"(v.z));
  asm("cvt.rna.tf32.f32 %0, %1;" : "=r"(t3) : "f"(v.w));
  int e = i << 2;
  int iw0 = e & 63;                          // multiple of 4
  int rowb = e & ~63;                        // row base (64 floats per row)
  float2* pe = (float2*)(xT + rowb + (iw0 >> 1));
  float2* po = (float2*)(xT + rowb + 32 + (iw0 >> 1));
  *pe = make_float2(__uint_as_float(t0), __uint_as_float(t2));
  *po = make_float2(__uint_as_float(t1), __uint_as_float(t3));
}

__global__ void prep_w(const float* __restrict__ w) {
  int i = blockIdx.x * 256 + threadIdx.x;   // grid covers 589824
  float v = w[i];
  uint32_t t;
  asm("cvt.rna.tf32.f32 %0, %1;" : "=r"(t) : "f"(v));
  int n = i / 2304;
  int r = i - n * 2304;
  int cin = r / 9;
  int t9 = r - cin * 9;
  int kp = t9 * 256 + cin;                   // k'
  int s = kp >> 4, c = kp & 15;
  wT[s * 4096 + (n >> 3) * 128 + (n & 7) * 16 + (c & 3) * 4 + (c >> 2)] =
      __uint_as_float(t);
}

__device__ __forceinline__ void lds128(uint32_t* r, uint32_t a) {
  asm volatile("ld.shared.v4.b32 {%0,%1,%2,%3}, [%4];"
               : "=r"(r[0]), "=r"(r[1]), "=r"(r[2]), "=r"(r[3]) : "r"(a));
}
__device__ __forceinline__ void mma8(float* c, const uint32_t* a, uint32_t b0, uint32_t b1) {
  asm volatile(
      "mma.sync.aligned.m16n8k8.row.col.f32.tf32.tf32.f32 "
      "{%0,%1,%2,%3}, {%4,%5,%6,%7}, {%8,%9}, {%0,%1,%2,%3};"
      : "+f"(c[0]), "+f"(c[1]), "+f"(c[2]), "+f"(c[3])
      : "r"(a[0]), "r"(a[1]), "r"(a[2]), "r"(a[3]), "r"(b0), "r"(b1));
}

__global__ __launch_bounds__(256, 2)
void conv_main(float* __restrict__ out) {
  extern __shared__ char dsm[];
  const uint32_t sb = smem_u32(dsm);
  const int tid = threadIdx.x, lane = tid & 31, warp = tid >> 5;
  const int wm = warp & 1, wn = warp >> 1;   // 2 (M, 64 rows) x 4 (N, 32 cols)
  const int m0 = blockIdx.x * 128;
  const int n0 = blockIdx.y * 128;
  const int bimg = m0 >> 10;

  // ---- producer-side constants (thread = row r, k-half ks) ----
  const int pr = tid >> 1;                   // 0..127
  const int pks = tid & 1;
  const int pm = m0 + pr;
  const int poh = (pm >> 5) & 31, pow_ = pm & 31;
  const int prr = pr & 15;
  const uint32_t a_off = (uint32_t)(((pr >> 4) * 2 + pks) * 512 + (prr & 7) * 64
                                    + (prr >> 3) * 4);
  const float* xb = xT + ((size_t)bimg * 256) * 4096;

  float acc[4][4][4];
#pragma unroll
  for (int mi = 0; mi < 4; ++mi)
#pragma unroll
    for (int ni = 0; ni < 4; ++ni)
#pragma unroll
      for (int q = 0; q < 4; ++q) acc[mi][ni][q] = 0.f;

  auto load_stage = [&](int s, int buf) {
    // ---- A: 8x 4B cp.async into fragment slots, single predicate ----
    const int tap = s >> 4;
    const int cinb = (s & 15) << 4;
    const int kh = tap / 3, kw = tap - kh * 3;
    const int ih = 2 * poh - 1 + kh;
    const int iw = 2 * pow_ - 1 + kw;
    const bool ok = ((unsigned)ih < 64u) && ((unsigned)iw < 64u);
    const float* src = ok ? (xb + (size_t)(cinb + pks * 8) * 4096 + ih * 64
                             + (iw & 1) * 32 + (iw >> 1))
                          : (const float*)xT;
    const int sz = ok ? 4 : 0;
    const uint32_t ab = sb + SM_A + buf * A_STAGE + a_off;
#pragma unroll
    for (int half = 0; half < 2; ++half)
#pragma unroll
      for (int tg = 0; tg < 4; ++tg) {
        const uint32_t dst = ab + tg * 16 + half * 8;
        const float* sp = src + (size_t)(half * 4 + tg) * 4096;
        asm volatile("cp.async.ca.shared.global [%0], [%1], 4, %2;\n"
                     :: "r"(dst), "l"(sp), "r"(sz));
      }
    // ---- B: identity copy of this CTA's 8KB n-half of the stage block ----
    const float* bsrc = wT + (size_t)s * 4096 + (size_t)blockIdx.y * 2048 + tid * 8;
    const uint32_t bdst = sb + SM_B + buf * B_STAGE + tid * 32;
    asm volatile("cp.async.cg.shared.global [%0], [%1], 16;\n"
                 :: "r"(bdst), "l"(bsrc));
    asm volatile("cp.async.cg.shared.global [%0], [%1], 16;\n"
                 :: "r"(bdst + 16), "l"(bsrc + 4));
  };

  load_stage(0, 0);
  asm volatile("cp.async.commit_group;\n");
  load_stage(1, 1);
  asm volatile("cp.async.commit_group;\n");

  int buf = 0, buf2 = 2;   // buf = s%3, buf2 = (s+2)%3
  for (int s = 0; s < NIT; ++s) {
    asm volatile("cp.async.wait_group 1;\n" ::: "memory");
    __syncthreads();
    if (s + 2 < NIT) load_stage(s + 2, buf2);
    asm volatile("cp.async.commit_group;\n");

    const uint32_t ab = sb + SM_A + buf * A_STAGE + wm * 4096 + lane * 16;
    const uint32_t bb = sb + SM_B + buf * B_STAGE + wn * 2048 + lane * 16;
    uint32_t a[4][2][4];
#pragma unroll
    for (int mi = 0; mi < 4; ++mi)
#pragma unroll
      for (int ks = 0; ks < 2; ++ks)
        lds128(a[mi][ks], ab + (mi * 2 + ks) * 512);
#pragma unroll
    for (int ni = 0; ni < 4; ++ni) {
      uint32_t b[4];
      lds128(b, bb + ni * 512);
#pragma unroll
      for (int mi = 0; mi < 4; ++mi) {
        mma8(acc[mi][ni], a[mi][0], b[0], b[1]);
        mma8(acc[mi][ni], a[mi][1], b[2], b[3]);
      }
    }
    buf = (buf == 2) ? 0 : buf + 1;
    buf2 = (buf2 == 2) ? 0 : buf2 + 1;
  }

  // ---- epilogue: out[b][n][oh][ow] ----
  const int g = lane >> 2, tg = lane & 3;
#pragma unroll
  for (int mi = 0; mi < 4; ++mi) {
    const int mrow = m0 + wm * 64 + mi * 16 + g;
    const int sp = mrow & 1023;
#pragma unroll
    for (int ni = 0; ni < 4; ++ni) {
      const int n = n0 + wn * 32 + ni * 8 + 2 * tg;
      float* o0 = out + ((size_t)bimg * 256 + n) * 1024;
      o0[sp]            = acc[mi][ni][0];
      o0[1024 + sp]     = acc[mi][ni][1];
      o0[sp + 8]        = acc[mi][ni][2];
      o0[1024 + sp + 8] = acc[mi][ni][3];
    }
  }
}

extern "C" void kernel_launch(void* const* d_in, const int* in_sizes, int n_in,
                              void* d_out, int out_size) {
  (void)out_size;
  const float* x = (const float*)d_in[0];
  const float* w = (const float*)d_in[1];
  if (n_in >= 2 && in_sizes[0] < in_sizes[1]) {  // defensive ordering by size
    x = (const float*)d_in[1];
    w = (const float*)d_in[0];
  }
  cudaFuncSetAttribute(conv_main, cudaFuncAttributeMaxDynamicSharedMemorySize,
                       SMEM_BYTES);
  prep_x<<<32768, 256>>>((const float4*)x);
  prep_w<<<2304, 256>>>(w);
  dim3 grid(256, 2);
  conv_main<<<grid, 256, SMEM_BYTES>>>((float*)d_out);
}